// round 1
// baseline (speedup 1.0000x reference)
#include <cuda_runtime.h>
#include <math.h>

#define DIM   128
#define HID   384
#define HC    128
#define BB    4
#define ND    100000
#define NTOK  400000
#define NL    4096
#define EE    200000
#define EPS   1e-5f
#define TM    64
#define XS_STRIDE 129

// ---------------- scratch (device globals; no allocations allowed) ----------
__device__ float g_vact[(size_t)NTOK * DIM];      // 204.8 MB
__device__ float g_l[(size_t)BB * NL * DIM];      // 8.4 MB
__device__ int   g_hist[NL];
__device__ int   g_cursor[NL];
__device__ int   g_seg_start[NL + 1];
__device__ int   g_sorted[EE];

typedef unsigned long long u64;

__device__ __forceinline__ u64 pack2(float lo, float hi) {
    u64 r; asm("mov.b64 %0, {%1, %2};" : "=l"(r) : "f"(lo), "f"(hi)); return r;
}
__device__ __forceinline__ void unpack2(u64 v, float& lo, float& hi) {
    asm("mov.b64 {%0, %1}, %2;" : "=f"(lo), "=f"(hi) : "l"(v));
}
// packed fp32x2 FMA (2 FMAs/instr on sm_103a; ptxas never auto-fuses this)
__device__ __forceinline__ void fma2(u64& d, u64 a, u64 b) {
    asm("fma.rn.f32x2 %0, %1, %2, %0;" : "+l"(d) : "l"(a), "l"(b));
}

// ---------------------------------------------------------------------------
// Fused gated-FFN core: for 64 rows of x starting at row0 computes
//   y = (silu(xn@w1) * (xn@w3)) @ w2,  xn = rmsnorm(x)*rw
// y[i][2q+hf] holds cols {4tx+32q+2hf, +1} of rows {2ty, 2ty+1}.
// ---------------------------------------------------------------------------
__device__ __forceinline__ void ffn_core(
    const float* __restrict__ x, int row0,
    const float* __restrict__ rw,
    const float* __restrict__ w1, const float* __restrict__ w2,
    const float* __restrict__ w3,
    float* xs, float* wa, float* wb, float* as_,
    u64 (&y)[2][8])
{
    const int tid = threadIdx.x;
    const int tx = tid & 7;
    const int ty = tid >> 3;

    // ---- load x tile + rmsnorm: 4 threads per row, 32 elems each ----
    {
        int r   = tid >> 2;
        int seg = tid & 3;
        const float* xr = x + (size_t)(row0 + r) * DIM + seg * 32;
        float vals[32];
        float ssq = 0.f;
        #pragma unroll
        for (int i = 0; i < 32; i += 4) {
            float4 v4 = *(const float4*)(xr + i);
            vals[i] = v4.x; vals[i+1] = v4.y; vals[i+2] = v4.z; vals[i+3] = v4.w;
            ssq += v4.x*v4.x + v4.y*v4.y + v4.z*v4.z + v4.w*v4.w;
        }
        ssq += __shfl_xor_sync(0xffffffffu, ssq, 1);
        ssq += __shfl_xor_sync(0xffffffffu, ssq, 2);
        float inv = rsqrtf(ssq * (1.0f / DIM) + EPS);
        #pragma unroll
        for (int i = 0; i < 32; i++)
            xs[r * XS_STRIDE + seg * 32 + i] = vals[i] * inv * rw[seg * 32 + i];
    }

    #pragma unroll
    for (int i = 0; i < 2; i++) {
        #pragma unroll
        for (int p = 0; p < 8; p++) y[i][p] = 0ull;
    }

    for (int c = 0; c < 3; c++) {
        __syncthreads();   // protects wa/wb vs previous phase readers; xs ready
        // ---- stage w1, w3 chunks into smem ----
        {
            int k = tid >> 1;
            int half = tid & 1;
            const float* s1 = w1 + (size_t)k * HID + c * HC + half * 64;
            const float* s3 = w3 + (size_t)k * HID + c * HC + half * 64;
            float* d1 = wa + k * HC + half * 64;
            float* d3 = wb + k * HC + half * 64;
            #pragma unroll
            for (int i = 0; i < 64; i += 4) {
                *(float4*)(d1 + i) = *(const float4*)(s1 + i);
                *(float4*)(d3 + i) = *(const float4*)(s3 + i);
            }
        }
        __syncthreads();

        // ---- h = xn@w1c, g = xn@w3c ----
        u64 h[2][8], g[2][8];
        #pragma unroll
        for (int i = 0; i < 2; i++) {
            #pragma unroll
            for (int p = 0; p < 8; p++) { h[i][p] = 0ull; g[i][p] = 0ull; }
        }
        #pragma unroll 2
        for (int k = 0; k < HC; k++) {
            float x0 = xs[(2*ty + 0) * XS_STRIDE + k];
            float x1 = xs[(2*ty + 1) * XS_STRIDE + k];
            u64 xx0 = pack2(x0, x0), xx1 = pack2(x1, x1);
            #pragma unroll
            for (int q = 0; q < 4; q++) {
                ulonglong2 wv1 = *(const ulonglong2*)(wa + k * HC + 4*tx + 32*q);
                ulonglong2 wv3 = *(const ulonglong2*)(wb + k * HC + 4*tx + 32*q);
                fma2(h[0][2*q],   xx0, wv1.x); fma2(h[0][2*q+1], xx0, wv1.y);
                fma2(h[1][2*q],   xx1, wv1.x); fma2(h[1][2*q+1], xx1, wv1.y);
                fma2(g[0][2*q],   xx0, wv3.x); fma2(g[0][2*q+1], xx0, wv3.y);
                fma2(g[1][2*q],   xx1, wv3.x); fma2(g[1][2*q+1], xx1, wv3.y);
            }
        }

        // ---- a = silu(h)*g -> smem ----
        #pragma unroll
        for (int i = 0; i < 2; i++) {
            #pragma unroll
            for (int q = 0; q < 4; q++) {
                #pragma unroll
                for (int hf = 0; hf < 2; hf++) {
                    float h0, h1, g0, g1;
                    unpack2(h[i][2*q+hf], h0, h1);
                    unpack2(g[i][2*q+hf], g0, g1);
                    float a0 = h0 / (1.f + __expf(-h0)) * g0;
                    float a1 = h1 / (1.f + __expf(-h1)) * g1;
                    float* dst = as_ + (2*ty + i) * XS_STRIDE + 4*tx + 32*q + 2*hf;
                    dst[0] = a0; dst[1] = a1;
                }
            }
        }
        __syncthreads();
        // ---- stage w2 chunk into wa (hg-gemm done by all threads) ----
        {
            int j = tid >> 1;
            int half = tid & 1;
            const float* s2 = w2 + (size_t)(c * HC + j) * DIM + half * 64;
            float* d2 = wa + j * DIM + half * 64;
            #pragma unroll
            for (int i = 0; i < 64; i += 4)
                *(float4*)(d2 + i) = *(const float4*)(s2 + i);
        }
        __syncthreads();
        // ---- y += a @ w2c ----
        #pragma unroll 2
        for (int j = 0; j < HC; j++) {
            float a0 = as_[(2*ty + 0) * XS_STRIDE + j];
            float a1 = as_[(2*ty + 1) * XS_STRIDE + j];
            u64 aa0 = pack2(a0, a0), aa1 = pack2(a1, a1);
            #pragma unroll
            for (int q = 0; q < 4; q++) {
                ulonglong2 wv = *(const ulonglong2*)(wa + j * DIM + 4*tx + 32*q);
                fma2(y[0][2*q], aa0, wv.x); fma2(y[0][2*q+1], aa0, wv.y);
                fma2(y[1][2*q], aa1, wv.x); fma2(y[1][2*q+1], aa1, wv.y);
            }
        }
    }
}

// ---------------------------------------------------------------------------
// Stage 1: v_act = tanh(ffn(rmsnorm(v)) + v)
// ---------------------------------------------------------------------------
__global__ void __launch_bounds__(256, 1) ffn1_kernel(
    const float* __restrict__ v, const float* __restrict__ rw,
    const float* __restrict__ w1, const float* __restrict__ w2,
    const float* __restrict__ w3)
{
    extern __shared__ float sm[];
    float* xs  = sm;
    float* wa  = xs + TM * XS_STRIDE;
    float* wb  = wa + HC * HC;
    float* as_ = wb + HC * HC;
    int row0 = blockIdx.x * TM;

    u64 y[2][8];
    ffn_core(v, row0, rw, w1, w2, w3, xs, wa, wb, as_, y);

    const int tx = threadIdx.x & 7, ty = threadIdx.x >> 3;
    #pragma unroll
    for (int i = 0; i < 2; i++) {
        int row = row0 + 2*ty + i;
        const float* vr   = v      + (size_t)row * DIM;
        float*       outr = g_vact + (size_t)row * DIM;
        #pragma unroll
        for (int q = 0; q < 4; q++) {
            #pragma unroll
            for (int hf = 0; hf < 2; hf++) {
                int col = 4*tx + 32*q + 2*hf;
                float ylo, yhi; unpack2(y[i][2*q+hf], ylo, yhi);
                float2 res = *(const float2*)(vr + col);
                float2 o;
                o.x = tanhf(ylo + res.x);
                o.y = tanhf(yhi + res.y);
                *(float2*)(outr + col) = o;
            }
        }
    }
}

// ---------------------------------------------------------------------------
// Segment machinery: histogram -> scan -> scatter (edge ids) -> product
// ---------------------------------------------------------------------------
__global__ void init_hist_kernel() {
    int i = blockIdx.x * blockDim.x + threadIdx.x;
    if (i < NL) g_hist[i] = 0;
}

__global__ void hist_kernel(const int* __restrict__ dd) {
    int e = blockIdx.x * blockDim.x + threadIdx.x;
    if (e < EE) atomicAdd(&g_hist[dd[e]], 1);
}

__global__ void scan_kernel() {
    __shared__ int sdata[1024];
    int tid = threadIdx.x;               // 1024 threads, 4 bins each
    int base = tid * 4;
    int s0 = g_hist[base], s1 = g_hist[base+1], s2 = g_hist[base+2], s3 = g_hist[base+3];
    int tsum = s0 + s1 + s2 + s3;
    sdata[tid] = tsum;
    __syncthreads();
    for (int off = 1; off < 1024; off <<= 1) {
        int v_ = sdata[tid];
        int u  = (tid >= off) ? sdata[tid - off] : 0;
        __syncthreads();
        sdata[tid] = v_ + u;
        __syncthreads();
    }
    int excl = sdata[tid] - tsum;
    int o0 = excl, o1 = excl + s0, o2 = excl + s0 + s1, o3 = excl + s0 + s1 + s2;
    g_seg_start[base]   = o0;  g_cursor[base]   = o0;
    g_seg_start[base+1] = o1;  g_cursor[base+1] = o1;
    g_seg_start[base+2] = o2;  g_cursor[base+2] = o2;
    g_seg_start[base+3] = o3;  g_cursor[base+3] = o3;
    if (tid == 1023) g_seg_start[NL] = sdata[1023];
}

__global__ void scatter_kernel(const int* __restrict__ dd) {
    int e = blockIdx.x * blockDim.x + threadIdx.x;
    if (e < EE) {
        int pos = atomicAdd(&g_cursor[dd[e]], 1);
        g_sorted[pos] = e;   // store edge index; sorted per-segment later
    }
}

// one block per segment, 512 threads = 4 batches x 128 dims
__global__ void __launch_bounds__(512) segprod_kernel(const int* __restrict__ ds) {
    __shared__ int sidx[512];
    __shared__ int ssrc[512];
    int s   = blockIdx.x;
    int tid = threadIdx.x;
    int b   = tid >> 7;
    int d   = tid & 127;
    int start = g_seg_start[s], end = g_seg_start[s + 1];
    int n = end - start;
    float p0 = 1.f, p1 = 1.f, p2 = 1.f, p3 = 1.f;

    if (n <= 512) {
        if (tid < n) sidx[tid] = g_sorted[start + tid];
        __syncthreads();
        // odd-even transposition sort (deterministic product order)
        for (int pass = 0; pass < n; pass++) {
            int i = 2 * tid + (pass & 1);
            if (i + 1 < n) {
                int a = sidx[i], bb = sidx[i + 1];
                if (a > bb) { sidx[i] = bb; sidx[i + 1] = a; }
            }
            __syncthreads();
        }
        if (tid < n) ssrc[tid] = ds[sidx[tid]];
        __syncthreads();
        const float* vb = g_vact + (size_t)b * ND * DIM + d;
        int i = 0;
        for (; i + 4 <= n; i += 4) {
            p0 *= vb[(size_t)ssrc[i]     * DIM];
            p1 *= vb[(size_t)ssrc[i + 1] * DIM];
            p2 *= vb[(size_t)ssrc[i + 2] * DIM];
            p3 *= vb[(size_t)ssrc[i + 3] * DIM];
        }
        for (; i < n; i++) p0 *= vb[(size_t)ssrc[i] * DIM];
    } else {
        // pathological fallback (unsorted, chunked)
        const float* vb = g_vact + (size_t)b * ND * DIM + d;
        for (int basee = start; basee < end; basee += 512) {
            int cnt = min(512, end - basee);
            __syncthreads();
            if (tid < cnt) ssrc[tid] = ds[g_sorted[basee + tid]];
            __syncthreads();
            for (int i = 0; i < cnt; i++) p0 *= vb[(size_t)ssrc[i] * DIM];
        }
    }
    g_l[((size_t)b * NL + s) * DIM + d] = p0 * p1 * p2 * p3;
}

// ---------------------------------------------------------------------------
// Stage 3: out = (ffn(rmsnorm(l)) + l) @ wout + bout
// ---------------------------------------------------------------------------
__global__ void __launch_bounds__(256, 1) ffn2_kernel(
    const float* __restrict__ rw,
    const float* __restrict__ w1, const float* __restrict__ w2,
    const float* __restrict__ w3,
    const float* __restrict__ wout, const float* __restrict__ bout,
    float* __restrict__ out)
{
    extern __shared__ float sm[];
    float* xs  = sm;
    float* wa  = xs + TM * XS_STRIDE;
    float* wb  = wa + HC * HC;
    float* as_ = wb + HC * HC;
    int row0 = blockIdx.x * TM;

    u64 y[2][8];
    ffn_core(g_l, row0, rw, w1, w2, w3, xs, wa, wb, as_, y);

    const int tx = threadIdx.x & 7, ty = threadIdx.x >> 3;
    float acc0 = 0.f, acc1 = 0.f;
    #pragma unroll
    for (int q = 0; q < 4; q++) {
        #pragma unroll
        for (int hf = 0; hf < 2; hf++) {
            int col = 4*tx + 32*q + 2*hf;
            float y0l, y0h, y1l, y1h;
            unpack2(y[0][2*q+hf], y0l, y0h);
            unpack2(y[1][2*q+hf], y1l, y1h);
            float2 l0 = *(const float2*)(g_l + (size_t)(row0 + 2*ty)     * DIM + col);
            float2 l1 = *(const float2*)(g_l + (size_t)(row0 + 2*ty + 1) * DIM + col);
            float w0 = wout[col], w1v = wout[col + 1];
            acc0 += (y0l + l0.x) * w0 + (y0h + l0.y) * w1v;
            acc1 += (y1l + l1.x) * w0 + (y1h + l1.y) * w1v;
        }
    }
    #pragma unroll
    for (int m = 1; m < 8; m <<= 1) {
        acc0 += __shfl_xor_sync(0xffffffffu, acc0, m);
        acc1 += __shfl_xor_sync(0xffffffffu, acc1, m);
    }
    if (tx == 0) {
        float b0 = bout[0];
        out[row0 + 2*ty]     = acc0 + b0;
        out[row0 + 2*ty + 1] = acc1 + b0;
    }
}

// ---------------------------------------------------------------------------
extern "C" void kernel_launch(void* const* d_in, const int* in_sizes, int n_in,
                              void* d_out, int out_size)
{
    const float* v        = (const float*)d_in[0];
    const int*   data_src = (const int*)  d_in[1];
    const int*   data_dst = (const int*)  d_in[2];
    // num_logical may or may not be materialized as an input buffer
    int base = (n_in >= 14 && in_sizes[3] == 1) ? 4 : 3;
    const float* rms1_w = (const float*)d_in[base + 0];
    const float* w1a    = (const float*)d_in[base + 1];
    const float* w2a    = (const float*)d_in[base + 2];
    const float* w3a    = (const float*)d_in[base + 3];
    const float* rms2_w = (const float*)d_in[base + 4];
    const float* w1b    = (const float*)d_in[base + 5];
    const float* w2b    = (const float*)d_in[base + 6];
    const float* w3b    = (const float*)d_in[base + 7];
    const float* wout   = (const float*)d_in[base + 8];
    const float* bout   = (const float*)d_in[base + 9];
    float* out = (float*)d_out;

    const int SMEM_BYTES = (TM * XS_STRIDE + 2 * HC * HC + TM * XS_STRIDE) * 4; // 197120
    cudaFuncSetAttribute(ffn1_kernel, cudaFuncAttributeMaxDynamicSharedMemorySize, SMEM_BYTES);
    cudaFuncSetAttribute(ffn2_kernel, cudaFuncAttributeMaxDynamicSharedMemorySize, SMEM_BYTES);

    // segment bucketing (independent of ffn1; serial stream order is fine)
    init_hist_kernel<<<(NL + 255) / 256, 256>>>();
    hist_kernel<<<(EE + 1023) / 1024, 1024>>>(data_dst);
    scan_kernel<<<1, 1024>>>();
    scatter_kernel<<<(EE + 1023) / 1024, 1024>>>(data_dst);

    // stage 1
    ffn1_kernel<<<NTOK / TM, 256, SMEM_BYTES>>>(v, rms1_w, w1a, w2a, w3a);

    // stage 2
    segprod_kernel<<<NL, 512>>>(data_src);

    // stage 3 + readout
    ffn2_kernel<<<(BB * NL) / TM, 256, SMEM_BYTES>>>(rms2_w, w1b, w2b, w3b, wout, bout, out);
}

// round 6
// speedup vs baseline: 6.5069x; 6.5069x over previous
#include <cuda_runtime.h>
#include <cstdint>
#include <math.h>

#define DIM   128
#define HID   384
#define BB    4
#define ND    100000
#define NTOK  400000
#define NL    4096
#define EE    200000
#define EPS   1e-5f

// ---------------- scratch (device globals; no allocations allowed) ----------
// NOTE: these symbols must ONLY be referenced from device code. Passing them
// as kernel arguments from host code silently binds the host shadow address
// (ATS makes the store "succeed" into host RAM) — that was the Round-4/5 bug.
__device__ float g_vact[(size_t)NTOK * DIM];        // 204.8 MB
__device__ float g_l[(size_t)BB * NL * DIM];        // 8.4 MB  (segment products)
__device__ float g_l2[(size_t)BB * NL * DIM];       // 8.4 MB  (ffn2 output)
__device__ float g_w1T[2][3 * 128 * 128];           // [set][c][n][k] tf32
__device__ float g_w3T[2][3 * 128 * 128];
__device__ float g_w2T[2][3 * 128 * 128];           // [set][c][d][j] tf32
__device__ int   g_hist[NL];
__device__ int   g_cursor[NL];
__device__ int   g_seg_start[NL + 1];
__device__ int   g_sorted[EE];

__device__ __forceinline__ uint32_t f2tf32(float x) {  // round-to-nearest tf32
    uint32_t r;
    asm("cvt.rna.tf32.f32 %0, %1;" : "=r"(r) : "f"(x));
    return r;
}

// warp-level tf32 MMA: D[16x8] += A[16x8] * B[8x8]  (row.col)
__device__ __forceinline__ void mma8(float (&d)[4], const uint32_t (&a)[4],
                                     const uint32_t (&b)[2]) {
    asm volatile(
        "mma.sync.aligned.m16n8k8.row.col.f32.tf32.tf32.f32 "
        "{%0,%1,%2,%3}, {%4,%5,%6,%7}, {%8,%9}, {%0,%1,%2,%3};"
        : "+f"(d[0]), "+f"(d[1]), "+f"(d[2]), "+f"(d[3])
        : "r"(a[0]), "r"(a[1]), "r"(a[2]), "r"(a[3]), "r"(b[0]), "r"(b[1]));
}

// ---------------------------------------------------------------------------
// Weight prep: transpose + tf32-round both FFN weight sets
//  g_w1T[set][(c*128+n)*128+k] = tf32(w1[k][c*128+n])   (w1: [DIM,HID])
//  g_w3T same; g_w2T[set][(c*128+d)*128+j] = tf32(w2[c*128+j][d])  (w2: [HID,DIM])
// ---------------------------------------------------------------------------
__global__ void prep_kernel(const float* __restrict__ w1a, const float* __restrict__ w2a,
                            const float* __restrict__ w3a, const float* __restrict__ w1b,
                            const float* __restrict__ w2b, const float* __restrict__ w3b) {
    int id = blockIdx.x * 256 + threadIdx.x;
    if (id >= 6 * 49152) return;
    int m   = id / 98304;          // 0:w1, 1:w3, 2:w2
    int r   = id % 98304;
    int set = r / 49152;
    int q   = r % 49152;
    int c   = q / 16384;
    int a_  = (q / 128) % 128;     // n (or d)
    int k   = q % 128;             // k (or j)
    int dst = (c * 128 + a_) * 128 + k;
    if (m == 0) {
        const float* w = set ? w1b : w1a;
        g_w1T[set][dst] = __uint_as_float(f2tf32(w[k * HID + c * 128 + a_]));
    } else if (m == 1) {
        const float* w = set ? w3b : w3a;
        g_w3T[set][dst] = __uint_as_float(f2tf32(w[k * HID + c * 128 + a_]));
    } else {
        const float* w = set ? w2b : w2a;
        g_w2T[set][dst] = __uint_as_float(f2tf32(w[(c * 128 + k) * DIM + a_]));
    }
}

// ---------------------------------------------------------------------------
// Tensor-core (mma.sync tf32) fused gated FFN over a 128-row tile.
//  MODE 0: reads param xin,  out = tanh(ffn(rmsnorm(x)) + x) -> g_vact
//  MODE 1: reads g_l,        out = ffn(rmsnorm(x)) + x       -> g_l2
//
// smem layout (bytes):
//  XS  @ 0       : x tile, tf32, [128 rows][stride 132]           (67584)
//  B1  @ 67584   : w1 chunk [64n][132] OR w2 chunk [128d][68]     (34816)
//  B2  @ 102400  : w3 chunk [64n][132]                            (34816)
//  AS  @ 137216  : activation chunk [128 rows][stride 68]         (34816)
//  total 172032
// 8 warps: wy = warp>>1 (M 32-row slab), wx = warp&1 (N half)
// ---------------------------------------------------------------------------
#define XS_OFF  0
#define B1_OFF  67584
#define B2_OFF  102400
#define AS_OFF  137216
#define SMEM_TC 172032
#define XSTR 132
#define ASTR 68

template <int MODE>
__global__ void __launch_bounds__(256, 1) ffn_mma_kernel(
    const float* __restrict__ xin, const float* __restrict__ rw)
{
    extern __shared__ char smem[];
    float*    xs  = (float*)(smem + XS_OFF);
    uint32_t* xsu = (uint32_t*)xs;
    uint32_t* b1u = (uint32_t*)(smem + B1_OFF);
    uint32_t* b2u = (uint32_t*)(smem + B2_OFF);
    uint32_t* asu = (uint32_t*)(smem + AS_OFF);

    const int tid  = threadIdx.x;
    const int lane = tid & 31;
    const int w    = tid >> 5;
    const int wy   = w >> 1;     // 0..3  (rows wy*32 .. +32)
    const int wx   = w & 1;      // 0..1
    const int gq   = lane >> 2;  // groupID 0..7
    const int tg   = lane & 3;   // threadID_in_group
    const int row0 = blockIdx.x * 128;

    // resolve buffers IN DEVICE CODE (symbol addresses valid here)
    const float* xbase   = (MODE == 0) ? xin    : g_l;
    float*       outbase = (MODE == 0) ? g_vact : g_l2;
    const int set = (MODE == 0) ? 0 : 1;
    const float* w1T = g_w1T[set];
    const float* w3T = g_w3T[set];
    const float* w2T = g_w2T[set];

    // ---- load x tile + rmsnorm -> xs (tf32); 2 threads per row ----
    {
        int r = tid >> 1, half = tid & 1;
        const float* xr = xbase + ((size_t)(row0 + r)) * DIM + half * 64;
        float vals[64];
        float ssq = 0.f;
        #pragma unroll
        for (int i = 0; i < 64; i += 4) {
            float4 v4 = *(const float4*)(xr + i);
            vals[i] = v4.x; vals[i+1] = v4.y; vals[i+2] = v4.z; vals[i+3] = v4.w;
            ssq += v4.x*v4.x + v4.y*v4.y + v4.z*v4.z + v4.w*v4.w;
        }
        ssq += __shfl_xor_sync(0xffffffffu, ssq, 1);
        float inv = rsqrtf(ssq * (1.0f / DIM) + EPS);
        uint32_t* dst = xsu + r * XSTR + half * 64;
        #pragma unroll
        for (int i = 0; i < 64; i++)
            dst[i] = f2tf32(vals[i] * inv * __ldg(rw + half * 64 + i));
    }

    float Y[2][8][4];
    #pragma unroll
    for (int mt = 0; mt < 2; mt++)
        #pragma unroll
        for (int nt = 0; nt < 8; nt++)
            #pragma unroll
            for (int e = 0; e < 4; e++) Y[mt][nt][e] = 0.f;

    for (int cc = 0; cc < 6; cc++) {
        const int c  = cc >> 1;
        const int n0 = (cc & 1) * 64;

        __syncthreads();   // prev iteration's readers of B1/B2/AS done; xs ready (cc=0)
        // ---- stage w1 chunk -> B1, w3 chunk -> B2 ([64 rows n][128 k], stride XSTR) ----
        {
            int n = tid >> 2, qr = tid & 3;
            const float4* s1 = (const float4*)(w1T + ((size_t)(c * 128 + n0 + n)) * 128 + qr * 32);
            const float4* s3 = (const float4*)(w3T + ((size_t)(c * 128 + n0 + n)) * 128 + qr * 32);
            float4* d1 = (float4*)((float*)b1u + n * XSTR + qr * 32);
            float4* d2 = (float4*)((float*)b2u + n * XSTR + qr * 32);
            #pragma unroll
            for (int i = 0; i < 8; i++) { d1[i] = s1[i]; d2[i] = s3[i]; }
        }
        __syncthreads();

        // ---- gemm1: h = x@w1c, g = x@w3c  (warp tile 32x32) ----
        float h[2][4][4], gg[2][4][4];
        #pragma unroll
        for (int mt = 0; mt < 2; mt++)
            #pragma unroll
            for (int nt = 0; nt < 4; nt++)
                #pragma unroll
                for (int e = 0; e < 4; e++) { h[mt][nt][e] = 0.f; gg[mt][nt][e] = 0.f; }

        #pragma unroll
        for (int ks = 0; ks < 16; ks++) {
            const int k0 = ks * 8;
            uint32_t a[2][4];
            #pragma unroll
            for (int mt = 0; mt < 2; mt++) {
                int r = wy * 32 + mt * 16 + gq;
                const uint32_t* xa = xsu + r * XSTR + k0 + tg;
                a[mt][0] = xa[0];
                a[mt][1] = xa[8 * XSTR];
                a[mt][2] = xa[4];
                a[mt][3] = xa[8 * XSTR + 4];
            }
            #pragma unroll
            for (int nt = 0; nt < 4; nt++) {
                int n = wx * 32 + nt * 8 + gq;
                const uint32_t* bp1 = b1u + n * XSTR + k0 + tg;
                const uint32_t* bp3 = b2u + n * XSTR + k0 + tg;
                uint32_t bf1[2] = { bp1[0], bp1[4] };
                uint32_t bf3[2] = { bp3[0], bp3[4] };
                #pragma unroll
                for (int mt = 0; mt < 2; mt++) {
                    mma8(h[mt][nt],  a[mt], bf1);
                    mma8(gg[mt][nt], a[mt], bf3);
                }
            }
        }

        // ---- a = silu(h)*g -> AS (tf32) ----
        #pragma unroll
        for (int mt = 0; mt < 2; mt++) {
            #pragma unroll
            for (int nt = 0; nt < 4; nt++) {
                int r   = wy * 32 + mt * 16 + gq;
                int col = wx * 32 + nt * 8 + tg * 2;
                float h0 = h[mt][nt][0], h1 = h[mt][nt][1];
                float h2 = h[mt][nt][2], h3 = h[mt][nt][3];
                uint2 lo, hi;
                lo.x = f2tf32(h0 / (1.f + __expf(-h0)) * gg[mt][nt][0]);
                lo.y = f2tf32(h1 / (1.f + __expf(-h1)) * gg[mt][nt][1]);
                hi.x = f2tf32(h2 / (1.f + __expf(-h2)) * gg[mt][nt][2]);
                hi.y = f2tf32(h3 / (1.f + __expf(-h3)) * gg[mt][nt][3]);
                *(uint2*)(asu + r * ASTR + col)       = lo;
                *(uint2*)(asu + (r + 8) * ASTR + col) = hi;
            }
        }
        __syncthreads();

        // ---- stage w2 chunk -> B1  ([128 rows d][64 j], stride ASTR) ----
        {
            int d = tid >> 1, jh = (tid & 1) * 32;
            const float4* s2 = (const float4*)(w2T + ((size_t)(c * 128 + d)) * 128 + n0 + jh);
            float4* dd = (float4*)((float*)b1u + d * ASTR + jh);
            #pragma unroll
            for (int i = 0; i < 8; i++) dd[i] = s2[i];
        }
        __syncthreads();

        // ---- gemm2: Y += a @ w2c  (warp tile 32x64, K=64) ----
        #pragma unroll
        for (int ks = 0; ks < 8; ks++) {
            const int k0 = ks * 8;
            uint32_t a[2][4];
            #pragma unroll
            for (int mt = 0; mt < 2; mt++) {
                int r = wy * 32 + mt * 16 + gq;
                const uint32_t* ap = asu + r * ASTR + k0 + tg;
                a[mt][0] = ap[0];
                a[mt][1] = ap[8 * ASTR];
                a[mt][2] = ap[4];
                a[mt][3] = ap[8 * ASTR + 4];
            }
            #pragma unroll
            for (int nt = 0; nt < 8; nt++) {
                int d = wx * 64 + nt * 8 + gq;
                const uint32_t* bp = b1u + d * ASTR + k0 + tg;
                uint32_t bf[2] = { bp[0], bp[4] };
                #pragma unroll
                for (int mt = 0; mt < 2; mt++)
                    mma8(Y[mt][nt], a[mt], bf);
            }
        }
    }
    __syncthreads();

    // ---- stage Y into XS (f32), then coalesced residual + activation + store ----
    #pragma unroll
    for (int mt = 0; mt < 2; mt++) {
        #pragma unroll
        for (int nt = 0; nt < 8; nt++) {
            int r   = wy * 32 + mt * 16 + gq;
            int col = wx * 64 + nt * 8 + tg * 2;
            *(float2*)(xs + r * XSTR + col)       = make_float2(Y[mt][nt][0], Y[mt][nt][1]);
            *(float2*)(xs + (r + 8) * XSTR + col) = make_float2(Y[mt][nt][2], Y[mt][nt][3]);
        }
    }
    __syncthreads();
    {
        int r = tid >> 1, half = tid & 1;
        const float* resr = xbase   + ((size_t)(row0 + r)) * DIM + half * 64;
        float*       outr = outbase + ((size_t)(row0 + r)) * DIM + half * 64;
        const float* yr   = xs + r * XSTR + half * 64;
        #pragma unroll
        for (int i = 0; i < 64; i += 4) {
            float4 y4 = *(const float4*)(yr + i);
            float4 r4 = *(const float4*)(resr + i);
            float4 o;
            if (MODE == 0) {
                o.x = tanhf(y4.x + r4.x); o.y = tanhf(y4.y + r4.y);
                o.z = tanhf(y4.z + r4.z); o.w = tanhf(y4.w + r4.w);
            } else {
                o.x = y4.x + r4.x; o.y = y4.y + r4.y;
                o.z = y4.z + r4.z; o.w = y4.w + r4.w;
            }
            *(float4*)(outr + i) = o;
        }
    }
}

// ---------------------------------------------------------------------------
// Segment machinery: histogram -> scan -> scatter (edge ids) -> product
// ---------------------------------------------------------------------------
__global__ void init_hist_kernel() {
    int i = blockIdx.x * blockDim.x + threadIdx.x;
    if (i < NL) g_hist[i] = 0;
}
__global__ void hist_kernel(const int* __restrict__ dd) {
    int e = blockIdx.x * blockDim.x + threadIdx.x;
    if (e < EE) atomicAdd(&g_hist[dd[e]], 1);
}
__global__ void scan_kernel() {
    __shared__ int sdata[1024];
    int tid = threadIdx.x;
    int base = tid * 4;
    int s0 = g_hist[base], s1 = g_hist[base+1], s2 = g_hist[base+2], s3 = g_hist[base+3];
    int tsum = s0 + s1 + s2 + s3;
    sdata[tid] = tsum;
    __syncthreads();
    for (int off = 1; off < 1024; off <<= 1) {
        int v_ = sdata[tid];
        int u  = (tid >= off) ? sdata[tid - off] : 0;
        __syncthreads();
        sdata[tid] = v_ + u;
        __syncthreads();
    }
    int excl = sdata[tid] - tsum;
    int o0 = excl, o1 = excl + s0, o2 = excl + s0 + s1, o3 = excl + s0 + s1 + s2;
    g_seg_start[base]   = o0;  g_cursor[base]   = o0;
    g_seg_start[base+1] = o1;  g_cursor[base+1] = o1;
    g_seg_start[base+2] = o2;  g_cursor[base+2] = o2;
    g_seg_start[base+3] = o3;  g_cursor[base+3] = o3;
    if (tid == 1023) g_seg_start[NL] = sdata[1023];
}
__global__ void scatter_kernel(const int* __restrict__ dd) {
    int e = blockIdx.x * blockDim.x + threadIdx.x;
    if (e < EE) {
        int pos = atomicAdd(&g_cursor[dd[e]], 1);
        g_sorted[pos] = e;
    }
}

// one block per segment, 512 threads = 4 batches x 128 dims
__global__ void __launch_bounds__(512) segprod_kernel(const int* __restrict__ ds) {
    __shared__ int sidx[512];
    __shared__ int ssrc[512];
    int s   = blockIdx.x;
    int tid = threadIdx.x;
    int b   = tid >> 7;
    int d   = tid & 127;
    int start = g_seg_start[s], end = g_seg_start[s + 1];
    int n = end - start;
    float p0 = 1.f, p1 = 1.f, p2 = 1.f, p3 = 1.f;

    if (n <= 512) {
        if (tid < n) sidx[tid] = g_sorted[start + tid];
        __syncthreads();
        for (int pass = 0; pass < n; pass++) {       // deterministic order
            int i = 2 * tid + (pass & 1);
            if (i + 1 < n) {
                int a = sidx[i], bb = sidx[i + 1];
                if (a > bb) { sidx[i] = bb; sidx[i + 1] = a; }
            }
            __syncthreads();
        }
        if (tid < n) ssrc[tid] = ds[sidx[tid]];
        __syncthreads();
        const float* vb = g_vact + (size_t)b * ND * DIM + d;
        int i = 0;
        for (; i + 4 <= n; i += 4) {
            p0 *= vb[(size_t)ssrc[i]     * DIM];
            p1 *= vb[(size_t)ssrc[i + 1] * DIM];
            p2 *= vb[(size_t)ssrc[i + 2] * DIM];
            p3 *= vb[(size_t)ssrc[i + 3] * DIM];
        }
        for (; i < n; i++) p0 *= vb[(size_t)ssrc[i] * DIM];
    } else {
        const float* vb = g_vact + (size_t)b * ND * DIM + d;
        for (int basee = start; basee < end; basee += 512) {
            int cnt = min(512, end - basee);
            __syncthreads();
            if (tid < cnt) ssrc[tid] = ds[g_sorted[basee + tid]];
            __syncthreads();
            for (int i = 0; i < cnt; i++) p0 *= vb[(size_t)ssrc[i] * DIM];
        }
    }
    g_l[((size_t)b * NL + s) * DIM + d] = p0 * p1 * p2 * p3;
}

// ---------------------------------------------------------------------------
// Readout: out[i] = dot(g_l2[i,:], wout) + bout   (one warp per row)
// ---------------------------------------------------------------------------
__global__ void readout_kernel(const float* __restrict__ wout,
                               const float* __restrict__ bout,
                               float* __restrict__ out) {
    int row  = blockIdx.x * 8 + (threadIdx.x >> 5);
    int lane = threadIdx.x & 31;
    float4 w = ((const float4*)wout)[lane];
    float4 x = *(const float4*)(g_l2 + (size_t)row * DIM + lane * 4);
    float acc = x.x * w.x + x.y * w.y + x.z * w.z + x.w * w.w;
    #pragma unroll
    for (int m = 16; m > 0; m >>= 1) acc += __shfl_xor_sync(0xffffffffu, acc, m);
    if (lane == 0) out[row] = acc + bout[0];
}

// ---------------------------------------------------------------------------
extern "C" void kernel_launch(void* const* d_in, const int* in_sizes, int n_in,
                              void* d_out, int out_size)
{
    const float* v        = (const float*)d_in[0];
    const int*   data_src = (const int*)  d_in[1];
    const int*   data_dst = (const int*)  d_in[2];
    int base = (n_in >= 14 && in_sizes[3] == 1) ? 4 : 3;
    const float* rms1_w = (const float*)d_in[base + 0];
    const float* w1a    = (const float*)d_in[base + 1];
    const float* w2a    = (const float*)d_in[base + 2];
    const float* w3a    = (const float*)d_in[base + 3];
    const float* rms2_w = (const float*)d_in[base + 4];
    const float* w1b    = (const float*)d_in[base + 5];
    const float* w2b    = (const float*)d_in[base + 6];
    const float* w3b    = (const float*)d_in[base + 7];
    const float* wout   = (const float*)d_in[base + 8];
    const float* bout   = (const float*)d_in[base + 9];
    float* out = (float*)d_out;

    cudaFuncSetAttribute(ffn_mma_kernel<0>, cudaFuncAttributeMaxDynamicSharedMemorySize, SMEM_TC);
    cudaFuncSetAttribute(ffn_mma_kernel<1>, cudaFuncAttributeMaxDynamicSharedMemorySize, SMEM_TC);

    // weight transpose + tf32 rounding
    prep_kernel<<<(6 * 49152 + 255) / 256, 256>>>(w1a, w2a, w3a, w1b, w2b, w3b);

    // segment bucketing
    init_hist_kernel<<<(NL + 255) / 256, 256>>>();
    hist_kernel<<<(EE + 1023) / 1024, 1024>>>(data_dst);
    scan_kernel<<<1, 1024>>>();
    scatter_kernel<<<(EE + 1023) / 1024, 1024>>>(data_dst);

    // stage 1: v_act = tanh(ffn(rmsnorm(v)) + v)  (writes g_vact in-kernel)
    ffn_mma_kernel<0><<<NTOK / 128, 256, SMEM_TC>>>(v, rms1_w);

    // stage 2: per-segment products (g_vact -> g_l in-kernel)
    segprod_kernel<<<NL, 512>>>(data_src);

    // stage 3: l2 = ffn(rmsnorm(l)) + l  (g_l -> g_l2 in-kernel), then readout
    ffn_mma_kernel<1><<<(BB * NL) / 128, 256, SMEM_TC>>>(nullptr, rms2_w);
    readout_kernel<<<(BB * NL) / 8, 256>>>(wout, bout, out);
}

// round 7
// speedup vs baseline: 10.8494x; 1.6674x over previous
#include <cuda_runtime.h>
#include <cuda_fp16.h>
#include <cstdint>
#include <math.h>

#define DIM   128
#define HID   384
#define BB    4
#define ND    100000
#define NTOK  400000
#define NL    4096
#define EE    200000
#define EPS   1e-5f

// ---------------- scratch (device globals; no allocations allowed) ----------
// NOTE: reference these symbols ONLY from device code (Round-5 ATS lesson).
__device__ float  g_vact[(size_t)NTOK * DIM];       // 204.8 MB
__device__ float  g_l[(size_t)BB * NL * DIM];       // 8.4 MB
__device__ float  g_l2[(size_t)BB * NL * DIM];      // 8.4 MB
__device__ __half g_w1h[2][3 * 128 * 128];          // [set][(c*128+n)*128+k]
__device__ __half g_w3h[2][3 * 128 * 128];
__device__ __half g_w2h[2][3 * 128 * 128];          // [set][(c*128+d)*128+j]
__device__ int    g_hist[NL];
__device__ int    g_cursor[NL];
__device__ int    g_seg_start[NL + 1];
__device__ int    g_sorted[EE];

// pack two f32 -> f16x2 (lo = first arg)
__device__ __forceinline__ uint32_t h2pack(float lo, float hi) {
    uint32_t r;
    asm("cvt.rn.f16x2.f32 %0, %1, %2;" : "=r"(r) : "f"(hi), "f"(lo));
    return r;
}

// warp MMA: D[16x8] += A[16x16] * B[16x8]  fp16 in, fp32 acc  (row.col)
__device__ __forceinline__ void mma16(float (&d)[4], const uint32_t (&a)[4],
                                      uint32_t b0, uint32_t b1) {
    asm volatile(
        "mma.sync.aligned.m16n8k16.row.col.f32.f16.f16.f32 "
        "{%0,%1,%2,%3}, {%4,%5,%6,%7}, {%8,%9}, {%0,%1,%2,%3};"
        : "+f"(d[0]), "+f"(d[1]), "+f"(d[2]), "+f"(d[3])
        : "r"(a[0]), "r"(a[1]), "r"(a[2]), "r"(a[3]), "r"(b0), "r"(b1));
}

#define LDSM4(r0, r1, r2, r3, addr) \
    asm volatile("ldmatrix.sync.aligned.m8n8.x4.shared.b16 {%0,%1,%2,%3}, [%4];" \
                 : "=r"(r0), "=r"(r1), "=r"(r2), "=r"(r3) : "r"(addr))

__device__ __forceinline__ uint32_t smem_u32(const void* p) {
    uint32_t a;
    asm("{ .reg .u64 t; cvta.to.shared.u64 t, %1; cvt.u32.u64 %0, t; }" : "=r"(a) : "l"(p));
    return a;
}

// ---------------------------------------------------------------------------
// Weight prep: transpose + fp16-round both FFN weight sets
// ---------------------------------------------------------------------------
__global__ void prep_kernel(const float* __restrict__ w1a, const float* __restrict__ w2a,
                            const float* __restrict__ w3a, const float* __restrict__ w1b,
                            const float* __restrict__ w2b, const float* __restrict__ w3b) {
    int id = blockIdx.x * 256 + threadIdx.x;
    if (id >= 6 * 49152) return;
    int m   = id / 98304;          // 0:w1, 1:w3, 2:w2
    int r   = id % 98304;
    int set = r / 49152;
    int q   = r % 49152;
    int c   = q / 16384;
    int a_  = (q / 128) % 128;     // n (or d)
    int k   = q % 128;             // k (or j)
    int dst = (c * 128 + a_) * 128 + k;
    if (m == 0) {
        const float* w = set ? w1b : w1a;
        g_w1h[set][dst] = __float2half_rn(w[k * HID + c * 128 + a_]);
    } else if (m == 1) {
        const float* w = set ? w3b : w3a;
        g_w3h[set][dst] = __float2half_rn(w[k * HID + c * 128 + a_]);
    } else {
        const float* w = set ? w2b : w2a;
        g_w2h[set][dst] = __float2half_rn(w[(c * 128 + k) * DIM + a_]);
    }
}

// ---------------------------------------------------------------------------
// fp16 mma.sync + ldmatrix fused gated FFN over a 128-row tile.
//  MODE 0: reads param xin,  out = tanh(ffn(rmsnorm(x)) + x) -> g_vact
//  MODE 1: reads g_l,        out = ffn(rmsnorm(x)) + x       -> g_l2
//
// smem (bytes):
//  XS @ 0      : x tile f16 [128][136]         34816
//  B1 @ 34816  : w1 [64][136] / w2 [128][72]   18432
//  B2 @ 53248  : w3 [64][136]                  17408
//  AS @ 70656  : act f16 [128][72]             18432
//  total 89088; Y f32 staging reuses [0..67584) at the end.
// 8 warps: wy = warp>>1 (32-row M slab), wx = warp&1 (N half)
// ---------------------------------------------------------------------------
#define XS_OFF  0
#define B1_OFF  34816
#define B2_OFF  53248
#define AS_OFF  70656
#define SMEM_TC 89088
#define XSTRH 136
#define ASTRH 72

template <int MODE>
__global__ void __launch_bounds__(256, 1) ffn_mma_kernel(
    const float* __restrict__ xin, const float* __restrict__ rw)
{
    extern __shared__ char smem[];
    const uint32_t sb = smem_u32(smem);

    const int tid  = threadIdx.x;
    const int lane = tid & 31;
    const int w    = tid >> 5;
    const int wy   = w >> 1;
    const int wx   = w & 1;
    const int gq   = lane >> 2;
    const int tg   = lane & 3;
    const int row0 = blockIdx.x * 128;

    const float* xbase   = (MODE == 0) ? xin    : g_l;
    float*       outbase = (MODE == 0) ? g_vact : g_l2;
    const int set = (MODE == 0) ? 0 : 1;
    const __half* w1h = g_w1h[set];
    const __half* w3h = g_w3h[set];
    const __half* w2h = g_w2h[set];

    // ---- load x tile + rmsnorm -> XS (f16); 2 threads per row ----
    {
        int r = tid >> 1, half = tid & 1;
        const float* xr = xbase + ((size_t)(row0 + r)) * DIM + half * 64;
        float vals[64];
        float ssq = 0.f;
        #pragma unroll
        for (int i = 0; i < 64; i += 4) {
            float4 v4 = *(const float4*)(xr + i);
            vals[i] = v4.x; vals[i+1] = v4.y; vals[i+2] = v4.z; vals[i+3] = v4.w;
            ssq += v4.x*v4.x + v4.y*v4.y + v4.z*v4.z + v4.w*v4.w;
        }
        ssq += __shfl_xor_sync(0xffffffffu, ssq, 1);
        float inv = rsqrtf(ssq * (1.0f / DIM) + EPS);
        uint32_t pk[32];
        #pragma unroll
        for (int i = 0; i < 32; i++) {
            float a0 = vals[2*i]     * inv * __ldg(rw + half * 64 + 2*i);
            float a1 = vals[2*i + 1] * inv * __ldg(rw + half * 64 + 2*i + 1);
            pk[i] = h2pack(a0, a1);
        }
        uint4* dst = (uint4*)(smem + XS_OFF + r * (XSTRH * 2) + half * 128);
        #pragma unroll
        for (int i = 0; i < 8; i++)
            dst[i] = make_uint4(pk[4*i], pk[4*i+1], pk[4*i+2], pk[4*i+3]);
    }

    // ---- warp-invariant ldmatrix lane addresses ----
    const int aRow = ((lane >> 3) & 1) * 8 + (lane & 7);
    const int aK   = (lane >> 4) * 8;
    const int bRow = ((lane >> 4) & 1) * 8 + (lane & 7);
    const int bK   = ((lane >> 3) & 1) * 8;
    const uint32_t ax0  = sb + XS_OFF + ((wy*32 +      aRow) * XSTRH + aK) * 2;
    const uint32_t ax1  = sb + XS_OFF + ((wy*32 + 16 + aRow) * XSTRH + aK) * 2;
    const uint32_t aas0 = sb + AS_OFF + ((wy*32 +      aRow) * ASTRH + aK) * 2;
    const uint32_t aas1 = sb + AS_OFF + ((wy*32 + 16 + aRow) * ASTRH + aK) * 2;
    const uint32_t bx1  = sb + B1_OFF + ((wx*32 + bRow) * XSTRH + bK) * 2;
    const uint32_t bx3  = sb + B2_OFF + ((wx*32 + bRow) * XSTRH + bK) * 2;
    const uint32_t bw2  = sb + B1_OFF + ((wx*64 + bRow) * ASTRH + bK) * 2;
    uint32_t* asu = (uint32_t*)(smem + AS_OFF);

    float Y[2][8][4];
    #pragma unroll
    for (int mt = 0; mt < 2; mt++)
        #pragma unroll
        for (int nt = 0; nt < 8; nt++)
            #pragma unroll
            for (int e = 0; e < 4; e++) Y[mt][nt][e] = 0.f;

    for (int cc = 0; cc < 6; cc++) {
        const int c  = cc >> 1;
        const int n0 = (cc & 1) * 64;

        __syncthreads();
        // ---- stage w1 -> B1, w3 -> B2 ([64 n][128 k] f16, stride 136) ----
        {
            int n = tid >> 2, qr = tid & 3;
            const uint4* s1 = (const uint4*)(w1h + ((size_t)(c*128 + n0 + n)) * 128 + qr * 32);
            const uint4* s3 = (const uint4*)(w3h + ((size_t)(c*128 + n0 + n)) * 128 + qr * 32);
            uint4* d1 = (uint4*)(smem + B1_OFF + n * (XSTRH*2) + qr * 64);
            uint4* d2 = (uint4*)(smem + B2_OFF + n * (XSTRH*2) + qr * 64);
            #pragma unroll
            for (int i = 0; i < 4; i++) { d1[i] = s1[i]; d2[i] = s3[i]; }
        }
        __syncthreads();

        // ---- gemm1: h = x@w1c, g = x@w3c (warp tile 32x32, K=128) ----
        float h[2][4][4], gg[2][4][4];
        #pragma unroll
        for (int mt = 0; mt < 2; mt++)
            #pragma unroll
            for (int nt = 0; nt < 4; nt++)
                #pragma unroll
                for (int e = 0; e < 4; e++) { h[mt][nt][e] = 0.f; gg[mt][nt][e] = 0.f; }

        #pragma unroll
        for (int ks = 0; ks < 8; ks++) {
            uint32_t af[2][4];
            LDSM4(af[0][0], af[0][1], af[0][2], af[0][3], ax0 + ks * 32);
            LDSM4(af[1][0], af[1][1], af[1][2], af[1][3], ax1 + ks * 32);
            #pragma unroll
            for (int ntp = 0; ntp < 2; ntp++) {
                uint32_t b1f[4], b3f[4];
                LDSM4(b1f[0], b1f[1], b1f[2], b1f[3], bx1 + ntp * (16*XSTRH*2) + ks * 32);
                LDSM4(b3f[0], b3f[1], b3f[2], b3f[3], bx3 + ntp * (16*XSTRH*2) + ks * 32);
                #pragma unroll
                for (int mt = 0; mt < 2; mt++) {
                    mma16(h[mt][2*ntp],    af[mt], b1f[0], b1f[1]);
                    mma16(h[mt][2*ntp+1],  af[mt], b1f[2], b1f[3]);
                    mma16(gg[mt][2*ntp],   af[mt], b3f[0], b3f[1]);
                    mma16(gg[mt][2*ntp+1], af[mt], b3f[2], b3f[3]);
                }
            }
        }

        // ---- a = silu(h)*g -> AS (f16) ----
        #pragma unroll
        for (int mt = 0; mt < 2; mt++) {
            #pragma unroll
            for (int nt = 0; nt < 4; nt++) {
                int r  = wy * 32 + mt * 16 + gq;
                int cu = wx * 16 + nt * 4 + tg;        // u32 column
                float h0 = h[mt][nt][0], h1 = h[mt][nt][1];
                float h2_ = h[mt][nt][2], h3 = h[mt][nt][3];
                float a0 = h0 / (1.f + __expf(-h0)) * gg[mt][nt][0];
                float a1 = h1 / (1.f + __expf(-h1)) * gg[mt][nt][1];
                float a2 = h2_ / (1.f + __expf(-h2_)) * gg[mt][nt][2];
                float a3 = h3 / (1.f + __expf(-h3)) * gg[mt][nt][3];
                asu[r * 36 + cu]       = h2pack(a0, a1);
                asu[(r + 8) * 36 + cu] = h2pack(a2, a3);
            }
        }
        __syncthreads();

        // ---- stage w2 chunk -> B1 ([128 d][64 j] f16, stride 72) ----
        {
            int d = tid >> 1, jh = tid & 1;
            const uint4* s2 = (const uint4*)(w2h + ((size_t)(c*128 + d)) * 128 + n0 + jh * 32);
            uint4* dd = (uint4*)(smem + B1_OFF + d * (ASTRH*2) + jh * 64);
            #pragma unroll
            for (int i = 0; i < 4; i++) dd[i] = s2[i];
        }
        __syncthreads();

        // ---- gemm2: Y += a @ w2c (warp tile 32x64, K=64) ----
        #pragma unroll
        for (int ks = 0; ks < 4; ks++) {
            uint32_t af[2][4];
            LDSM4(af[0][0], af[0][1], af[0][2], af[0][3], aas0 + ks * 32);
            LDSM4(af[1][0], af[1][1], af[1][2], af[1][3], aas1 + ks * 32);
            #pragma unroll
            for (int ntp = 0; ntp < 4; ntp++) {
                uint32_t bf[4];
                LDSM4(bf[0], bf[1], bf[2], bf[3], bw2 + ntp * (16*ASTRH*2) + ks * 32);
                #pragma unroll
                for (int mt = 0; mt < 2; mt++) {
                    mma16(Y[mt][2*ntp],   af[mt], bf[0], bf[1]);
                    mma16(Y[mt][2*ntp+1], af[mt], bf[2], bf[3]);
                }
            }
        }
    }
    __syncthreads();

    // ---- stage Y (f32, stride 132) into smem, then coalesced store ----
    float* xsf = (float*)smem;
    #pragma unroll
    for (int mt = 0; mt < 2; mt++) {
        #pragma unroll
        for (int nt = 0; nt < 8; nt++) {
            int r   = wy * 32 + mt * 16 + gq;
            int col = wx * 64 + nt * 8 + tg * 2;
            *(float2*)(xsf + r * 132 + col)       = make_float2(Y[mt][nt][0], Y[mt][nt][1]);
            *(float2*)(xsf + (r + 8) * 132 + col) = make_float2(Y[mt][nt][2], Y[mt][nt][3]);
        }
    }
    __syncthreads();
    {
        int r = tid >> 1, half = tid & 1;
        const float* resr = xbase   + ((size_t)(row0 + r)) * DIM + half * 64;
        float*       outr = outbase + ((size_t)(row0 + r)) * DIM + half * 64;
        const float* yr   = xsf + r * 132 + half * 64;
        #pragma unroll
        for (int i = 0; i < 64; i += 4) {
            float4 y4 = *(const float4*)(yr + i);
            float4 r4 = *(const float4*)(resr + i);
            float4 o;
            if (MODE == 0) {
                o.x = tanhf(y4.x + r4.x); o.y = tanhf(y4.y + r4.y);
                o.z = tanhf(y4.z + r4.z); o.w = tanhf(y4.w + r4.w);
            } else {
                o.x = y4.x + r4.x; o.y = y4.y + r4.y;
                o.z = y4.z + r4.z; o.w = y4.w + r4.w;
            }
            *(float4*)(outr + i) = o;
        }
    }
}

// ---------------------------------------------------------------------------
// Segment machinery: histogram -> scan -> scatter -> product
// ---------------------------------------------------------------------------
__global__ void init_hist_kernel() {
    int i = blockIdx.x * blockDim.x + threadIdx.x;
    if (i < NL) g_hist[i] = 0;
}
__global__ void hist_kernel(const int* __restrict__ dd) {
    int e = blockIdx.x * blockDim.x + threadIdx.x;
    if (e < EE) atomicAdd(&g_hist[dd[e]], 1);
}
__global__ void scan_kernel() {
    __shared__ int sdata[1024];
    int tid = threadIdx.x;
    int base = tid * 4;
    int s0 = g_hist[base], s1 = g_hist[base+1], s2 = g_hist[base+2], s3 = g_hist[base+3];
    int tsum = s0 + s1 + s2 + s3;
    sdata[tid] = tsum;
    __syncthreads();
    for (int off = 1; off < 1024; off <<= 1) {
        int v_ = sdata[tid];
        int u  = (tid >= off) ? sdata[tid - off] : 0;
        __syncthreads();
        sdata[tid] = v_ + u;
        __syncthreads();
    }
    int excl = sdata[tid] - tsum;
    int o0 = excl, o1 = excl + s0, o2 = excl + s0 + s1, o3 = excl + s0 + s1 + s2;
    g_seg_start[base]   = o0;  g_cursor[base]   = o0;
    g_seg_start[base+1] = o1;  g_cursor[base+1] = o1;
    g_seg_start[base+2] = o2;  g_cursor[base+2] = o2;
    g_seg_start[base+3] = o3;  g_cursor[base+3] = o3;
    if (tid == 1023) g_seg_start[NL] = sdata[1023];
}
__global__ void scatter_kernel(const int* __restrict__ dd) {
    int e = blockIdx.x * blockDim.x + threadIdx.x;
    if (e < EE) {
        int pos = atomicAdd(&g_cursor[dd[e]], 1);
        g_sorted[pos] = e;
    }
}

// one block per segment, 512 threads = 4 batches x 128 dims
__global__ void __launch_bounds__(512) segprod_kernel(const int* __restrict__ ds) {
    __shared__ int sidx[512];
    __shared__ int ssrc[512];
    int s   = blockIdx.x;
    int tid = threadIdx.x;
    int b   = tid >> 7;
    int d   = tid & 127;
    int start = g_seg_start[s], end = g_seg_start[s + 1];
    int n = end - start;
    float p0 = 1.f, p1 = 1.f, p2 = 1.f, p3 = 1.f;

    if (n <= 512) {
        if (tid < n) sidx[tid] = g_sorted[start + tid];
        __syncthreads();
        for (int pass = 0; pass < n; pass++) {       // deterministic order
            int i = 2 * tid + (pass & 1);
            if (i + 1 < n) {
                int a = sidx[i], bb = sidx[i + 1];
                if (a > bb) { sidx[i] = bb; sidx[i + 1] = a; }
            }
            __syncthreads();
        }
        if (tid < n) ssrc[tid] = ds[sidx[tid]];
        __syncthreads();
        const float* vb = g_vact + (size_t)b * ND * DIM + d;
        int i = 0;
        for (; i + 4 <= n; i += 4) {
            p0 *= vb[(size_t)ssrc[i]     * DIM];
            p1 *= vb[(size_t)ssrc[i + 1] * DIM];
            p2 *= vb[(size_t)ssrc[i + 2] * DIM];
            p3 *= vb[(size_t)ssrc[i + 3] * DIM];
        }
        for (; i < n; i++) p0 *= vb[(size_t)ssrc[i] * DIM];
    } else {
        const float* vb = g_vact + (size_t)b * ND * DIM + d;
        for (int basee = start; basee < end; basee += 512) {
            int cnt = min(512, end - basee);
            __syncthreads();
            if (tid < cnt) ssrc[tid] = ds[g_sorted[basee + tid]];
            __syncthreads();
            for (int i = 0; i < cnt; i++) p0 *= vb[(size_t)ssrc[i] * DIM];
        }
    }
    g_l[((size_t)b * NL + s) * DIM + d] = p0 * p1 * p2 * p3;
}

// ---------------------------------------------------------------------------
// Readout: out[i] = dot(g_l2[i,:], wout) + bout   (one warp per row)
// ---------------------------------------------------------------------------
__global__ void readout_kernel(const float* __restrict__ wout,
                               const float* __restrict__ bout,
                               float* __restrict__ out) {
    int row  = blockIdx.x * 8 + (threadIdx.x >> 5);
    int lane = threadIdx.x & 31;
    float4 w = ((const float4*)wout)[lane];
    float4 x = *(const float4*)(g_l2 + (size_t)row * DIM + lane * 4);
    float acc = x.x * w.x + x.y * w.y + x.z * w.z + x.w * w.w;
    #pragma unroll
    for (int m = 16; m > 0; m >>= 1) acc += __shfl_xor_sync(0xffffffffu, acc, m);
    if (lane == 0) out[row] = acc + bout[0];
}

// ---------------------------------------------------------------------------
extern "C" void kernel_launch(void* const* d_in, const int* in_sizes, int n_in,
                              void* d_out, int out_size)
{
    const float* v        = (const float*)d_in[0];
    const int*   data_src = (const int*)  d_in[1];
    const int*   data_dst = (const int*)  d_in[2];
    int base = (n_in >= 14 && in_sizes[3] == 1) ? 4 : 3;
    const float* rms1_w = (const float*)d_in[base + 0];
    const float* w1a    = (const float*)d_in[base + 1];
    const float* w2a    = (const float*)d_in[base + 2];
    const float* w3a    = (const float*)d_in[base + 3];
    const float* rms2_w = (const float*)d_in[base + 4];
    const float* w1b    = (const float*)d_in[base + 5];
    const float* w2b    = (const float*)d_in[base + 6];
    const float* w3b    = (const float*)d_in[base + 7];
    const float* wout   = (const float*)d_in[base + 8];
    const float* bout   = (const float*)d_in[base + 9];
    float* out = (float*)d_out;

    cudaFuncSetAttribute(ffn_mma_kernel<0>, cudaFuncAttributeMaxDynamicSharedMemorySize, SMEM_TC);
    cudaFuncSetAttribute(ffn_mma_kernel<1>, cudaFuncAttributeMaxDynamicSharedMemorySize, SMEM_TC);

    // weight transpose + fp16 rounding
    prep_kernel<<<(6 * 49152 + 255) / 256, 256>>>(w1a, w2a, w3a, w1b, w2b, w3b);

    // segment bucketing
    init_hist_kernel<<<(NL + 255) / 256, 256>>>();
    hist_kernel<<<(EE + 1023) / 1024, 1024>>>(data_dst);
    scan_kernel<<<1, 1024>>>();
    scatter_kernel<<<(EE + 1023) / 1024, 1024>>>(data_dst);

    // stage 1: v_act = tanh(ffn(rmsnorm(v)) + v)
    ffn_mma_kernel<0><<<NTOK / 128, 256, SMEM_TC>>>(v, rms1_w);

    // stage 2: per-segment products
    segprod_kernel<<<NL, 512>>>(data_src);

    // stage 3: l2 = ffn(rmsnorm(l)) + l, then readout
    ffn_mma_kernel<1><<<(BB * NL) / 128, 256, SMEM_TC>>>(nullptr, rms2_w);
    readout_kernel<<<(BB * NL) / 8, 256>>>(wout, bout, out);
}